// round 1
// baseline (speedup 1.0000x reference)
#include <cuda_runtime.h>
#include <cstdint>

// ---------------------------------------------------------------------------
// MambaBlock: B=2, T=1024, DM=1024, D=2048, N=16, K=4, DTR=128
// Inputs (metadata order):
//  0 x        (2,1024,1024) f32
//  1 rms_w    (1024)
//  2 in_W     (1024,4096)
//  3 in_b     (4096)
//  4 conv_w   (2048,4)
//  5 conv_b   (2048)
//  6 A_log    (2048,16)
//  7 dbc_W    (2048,160)
//  8 dbc_b    (160)
//  9 dup_W    (128,2048)
// 10 dup_b    (2048)
// 11 out_W    (2048,1024)
// 12 out_b    (1024)
// Output: (2,1024,1024) f32
// ---------------------------------------------------------------------------

#define DMv   1024
#define Dv    2048
#define Tv    1024
#define NROWS 2048     // B*T
#define NSTv  16

// Scratch layout (floats)
#define OFF_H      0u          // 2048*1024  = 2,097,152
#define OFF_PROJ   2097152u    // 2048*4096  = 8,388,608
#define OFF_X1C    10485760u   // 2048*2048  = 4,194,304
#define OFF_DBC    14680064u   // 2048*160   = 327,680
#define OFF_DELTA  15007744u   // 2048*2048  = 4,194,304
#define OFF_YMOD   19202048u   // 2048*2048  = 4,194,304
#define SCRATCH_FLOATS 23396352u

__device__ __align__(128) float g_scratch[SCRATCH_FLOATS];

__device__ __forceinline__ float silu_f(float v) {
    return v * (1.0f / (1.0f + __expf(-v)));
}

// ---------------------------------------------------------------------------
// RMSNorm: one block per row (2048 rows), 256 threads, 4 floats/thread
// ---------------------------------------------------------------------------
__global__ void __launch_bounds__(256) rmsnorm_k(
    const float* __restrict__ x, const float* __restrict__ w, float* __restrict__ out)
{
    int row = blockIdx.x;
    const float4* xr = reinterpret_cast<const float4*>(x + (size_t)row * DMv);
    float4 v = xr[threadIdx.x];
    float s = v.x * v.x + v.y * v.y + v.z * v.z + v.w * v.w;
    #pragma unroll
    for (int o = 16; o; o >>= 1) s += __shfl_xor_sync(0xffffffffu, s, o);
    __shared__ float ws[8];
    if ((threadIdx.x & 31) == 0) ws[threadIdx.x >> 5] = s;
    __syncthreads();
    float tot = 0.f;
    #pragma unroll
    for (int i = 0; i < 8; i++) tot += ws[i];
    float scale = rsqrtf(tot * (1.0f / (float)DMv) + 1e-6f);
    float4 wv = reinterpret_cast<const float4*>(w)[threadIdx.x];
    float4 o;
    o.x = v.x * scale * wv.x; o.y = v.y * scale * wv.y;
    o.z = v.z * scale * wv.z; o.w = v.w * scale * wv.w;
    reinterpret_cast<float4*>(out + (size_t)row * DMv)[threadIdx.x] = o;
}

// ---------------------------------------------------------------------------
// 128x128x16 register-tiled SGEMM. C[M,N] = A[M,K]@B[K,N] + bias, epilogues:
//   EPI 0: none    EPI 1: softplus    EPI 2: + residual (res[M,N])
// M % 128 == 0 required. N guarded at float4 granularity (N % 4 == 0).
// ---------------------------------------------------------------------------
template <int EPI>
__global__ void __launch_bounds__(256) gemm128_k(
    const float* __restrict__ A, const float* __restrict__ B,
    const float* __restrict__ bias, float* __restrict__ C,
    int M, int N, int Kd, int lda, const float* __restrict__ res)
{
    __shared__ float As[16][132];   // A^T tile, padded
    __shared__ float Bs[16][128];
    int tid = threadIdx.x;
    int bm = blockIdx.y * 128, bn = blockIdx.x * 128;
    int tx = tid & 15, ty = tid >> 4;
    float acc[8][8] = {};

    for (int kt = 0; kt < Kd; kt += 16) {
        // A tile: 128x16 = 512 float4
        #pragma unroll
        for (int i = 0; i < 2; i++) {
            int li = tid + i * 256;
            int r = li >> 2;
            int c4 = (li & 3) * 4;
            float4 v = *reinterpret_cast<const float4*>(&A[(size_t)(bm + r) * lda + kt + c4]);
            As[c4 + 0][r] = v.x; As[c4 + 1][r] = v.y;
            As[c4 + 2][r] = v.z; As[c4 + 3][r] = v.w;
        }
        // B tile: 16x128 = 512 float4
        #pragma unroll
        for (int i = 0; i < 2; i++) {
            int li = tid + i * 256;
            int r = li >> 5;
            int c4 = (li & 31) * 4;
            int col = bn + c4;
            float4 v = make_float4(0.f, 0.f, 0.f, 0.f);
            if (col < N) v = *reinterpret_cast<const float4*>(&B[(size_t)(kt + r) * N + col]);
            Bs[r][c4 + 0] = v.x; Bs[r][c4 + 1] = v.y;
            Bs[r][c4 + 2] = v.z; Bs[r][c4 + 3] = v.w;
        }
        __syncthreads();
        #pragma unroll
        for (int k = 0; k < 16; k++) {
            float4 a0 = *reinterpret_cast<const float4*>(&As[k][ty * 8]);
            float4 a1 = *reinterpret_cast<const float4*>(&As[k][ty * 8 + 4]);
            float4 b0 = *reinterpret_cast<const float4*>(&Bs[k][tx * 8]);
            float4 b1 = *reinterpret_cast<const float4*>(&Bs[k][tx * 8 + 4]);
            float ra[8] = {a0.x, a0.y, a0.z, a0.w, a1.x, a1.y, a1.z, a1.w};
            float rb[8] = {b0.x, b0.y, b0.z, b0.w, b1.x, b1.y, b1.z, b1.w};
            #pragma unroll
            for (int i = 0; i < 8; i++)
                #pragma unroll
                for (int j = 0; j < 8; j++)
                    acc[i][j] = fmaf(ra[i], rb[j], acc[i][j]);
        }
        __syncthreads();
    }

    #pragma unroll
    for (int i = 0; i < 8; i++) {
        int row = bm + ty * 8 + i;
        #pragma unroll
        for (int j = 0; j < 8; j++) {
            int col = bn + tx * 8 + j;
            if (col >= N) continue;
            float v = acc[i][j] + bias[col];
            if (EPI == 1) v = (v > 20.0f) ? v : log1pf(__expf(v));
            if (EPI == 2) v += res[(size_t)row * N + col];
            C[(size_t)row * N + col] = v;
        }
    }
}

// ---------------------------------------------------------------------------
// Small GEMM for skinny-N (dbc projection, N=160): 64x32x32 tiles.
// ---------------------------------------------------------------------------
__global__ void __launch_bounds__(256) gemm_small_k(
    const float* __restrict__ A, const float* __restrict__ B,
    const float* __restrict__ bias, float* __restrict__ C,
    int M, int N, int Kd, int lda)
{
    __shared__ float As[32][65];
    __shared__ float Bs[32][33];
    int tid = threadIdx.x;
    int bm = blockIdx.y * 64, bn = blockIdx.x * 32;
    int tx = tid & 15, ty = tid >> 4;
    float acc[4][2] = {};

    for (int kt = 0; kt < Kd; kt += 32) {
        #pragma unroll
        for (int i = 0; i < 8; i++) {
            int li = tid + i * 256;
            int r = li >> 5, cc = li & 31;
            As[cc][r] = A[(size_t)(bm + r) * lda + kt + cc];
        }
        #pragma unroll
        for (int i = 0; i < 4; i++) {
            int li = tid + i * 256;
            int r = li >> 5, cc = li & 31;
            int col = bn + cc;
            Bs[r][cc] = (col < N) ? B[(size_t)(kt + r) * N + col] : 0.f;
        }
        __syncthreads();
        #pragma unroll
        for (int k = 0; k < 32; k++) {
            float ra[4], rb[2];
            #pragma unroll
            for (int i = 0; i < 4; i++) ra[i] = As[k][ty * 4 + i];
            rb[0] = Bs[k][tx * 2]; rb[1] = Bs[k][tx * 2 + 1];
            #pragma unroll
            for (int i = 0; i < 4; i++) {
                acc[i][0] = fmaf(ra[i], rb[0], acc[i][0]);
                acc[i][1] = fmaf(ra[i], rb[1], acc[i][1]);
            }
        }
        __syncthreads();
    }
    #pragma unroll
    for (int i = 0; i < 4; i++) {
        int row = bm + ty * 4 + i;
        #pragma unroll
        for (int j = 0; j < 2; j++) {
            int col = bn + tx * 2 + j;
            if (col < N) C[(size_t)row * N + col] = acc[i][j] + bias[col];
        }
    }
}

// ---------------------------------------------------------------------------
// Depthwise causal conv (K=4) + SiLU. x1 = proj[:, 0:2048].
// ---------------------------------------------------------------------------
__global__ void __launch_bounds__(256) conv_silu_k(
    const float* __restrict__ proj, const float* __restrict__ cw,
    const float* __restrict__ cb, float* __restrict__ out)
{
    int d = blockIdx.x * 256 + threadIdx.x;
    int row = blockIdx.y;
    int t = row & (Tv - 1);
    int b = row >> 10;
    float4 w = *reinterpret_cast<const float4*>(cw + (size_t)d * 4);
    float acc = cb[d];
    const float* base = proj + (size_t)(b * Tv) * 4096 + d;
    if (t >= 3) acc = fmaf(base[(size_t)(t - 3) * 4096], w.x, acc);
    if (t >= 2) acc = fmaf(base[(size_t)(t - 2) * 4096], w.y, acc);
    if (t >= 1) acc = fmaf(base[(size_t)(t - 1) * 4096], w.z, acc);
    acc = fmaf(base[(size_t)t * 4096], w.w, acc);
    out[(size_t)row * Dv + d] = silu_f(acc);
}

// ---------------------------------------------------------------------------
// Selective scan. Block: 256 threads = 16 channels x 16 states, one b per
// blockIdx.y, 16 d-channels per blockIdx.x. Sequential over T in chunks of
// 128 with B/C staged in smem. Output fused with silu(g): ymod = silu(g)*y.
// ---------------------------------------------------------------------------
__global__ void __launch_bounds__(256) scan_k(
    const float* __restrict__ dbc, const float* __restrict__ delta,
    const float* __restrict__ x1c, const float* __restrict__ proj,
    const float* __restrict__ A_log, float* __restrict__ ymod)
{
    __shared__ float Bs[128][16];
    __shared__ float Cs[128][16];
    __shared__ float Ys[128][16];
    int tid = threadIdx.x;
    int n = tid & 15, grp = tid >> 4;
    int b = blockIdx.y;
    int d = blockIdx.x * 16 + grp;
    float An = -__expf(A_log[(size_t)d * NSTv + n]);   // == -(n+1)
    float h = 0.f;

    for (int c = 0; c < 8; c++) {
        __syncthreads();
        int t0 = c * 128;
        for (int idx = tid; idx < 2048; idx += 256) {
            int tl = idx >> 4, nn = idx & 15;
            size_t r = (size_t)(b * Tv + t0 + tl) * 160;
            Bs[tl][nn] = dbc[r + 128 + nn];
            Cs[tl][nn] = dbc[r + 144 + nn];
        }
        __syncthreads();
        const float* dl = delta + (size_t)(b * Tv + t0) * Dv + d;
        const float* xv = x1c  + (size_t)(b * Tv + t0) * Dv + d;
        #pragma unroll 4
        for (int tl = 0; tl < 128; tl++) {
            float de = dl[(size_t)tl * Dv];
            float xx = xv[(size_t)tl * Dv];
            float a = __expf(de * An);
            h = fmaf(a, h, de * Bs[tl][n] * xx);
            float p = h * Cs[tl][n];
            p += __shfl_xor_sync(0xffffffffu, p, 8);
            p += __shfl_xor_sync(0xffffffffu, p, 4);
            p += __shfl_xor_sync(0xffffffffu, p, 2);
            p += __shfl_xor_sync(0xffffffffu, p, 1);
            if (n == 0) Ys[tl][grp] = p;
        }
        __syncthreads();
        for (int idx = tid; idx < 2048; idx += 256) {
            int tl = idx >> 4, dl2 = idx & 15;
            int row = b * Tv + t0 + tl;
            int dd = blockIdx.x * 16 + dl2;
            float g = proj[(size_t)row * 4096 + 2048 + dd];
            ymod[(size_t)row * Dv + dd] = Ys[tl][dl2] * silu_f(g);
        }
    }
}

// ---------------------------------------------------------------------------
extern "C" void kernel_launch(void* const* d_in, const int* in_sizes, int n_in,
                              void* d_out, int out_size)
{
    const float* x      = (const float*)d_in[0];
    const float* rms_w  = (const float*)d_in[1];
    const float* in_W   = (const float*)d_in[2];
    const float* in_b   = (const float*)d_in[3];
    const float* conv_w = (const float*)d_in[4];
    const float* conv_b = (const float*)d_in[5];
    const float* A_log  = (const float*)d_in[6];
    const float* dbc_W  = (const float*)d_in[7];
    const float* dbc_b  = (const float*)d_in[8];
    const float* dup_W  = (const float*)d_in[9];
    const float* dup_b  = (const float*)d_in[10];
    const float* out_W  = (const float*)d_in[11];
    const float* out_b  = (const float*)d_in[12];
    float* out = (float*)d_out;

    float* S = nullptr;
    cudaGetSymbolAddress((void**)&S, g_scratch);

    // 1. RMSNorm
    rmsnorm_k<<<NROWS, 256>>>(x, rms_w, S + OFF_H);

    // 2. in_proj: (2048x1024)@(1024x4096)
    gemm128_k<0><<<dim3(4096 / 128, NROWS / 128), 256>>>(
        S + OFF_H, in_W, in_b, S + OFF_PROJ, NROWS, 4096, 1024, 1024, nullptr);

    // 3. depthwise conv + SiLU
    conv_silu_k<<<dim3(Dv / 256, NROWS), 256>>>(S + OFF_PROJ, conv_w, conv_b, S + OFF_X1C);

    // 4. dbc: (2048x2048)@(2048x160)
    gemm_small_k<<<dim3(160 / 32, NROWS / 64), 256>>>(
        S + OFF_X1C, dbc_W, dbc_b, S + OFF_DBC, NROWS, 160, 2048, 2048);

    // 5. delta up-proj + softplus: (2048x128)@(128x2048), A rows strided by 160
    gemm128_k<1><<<dim3(2048 / 128, NROWS / 128), 256>>>(
        S + OFF_DBC, dup_W, dup_b, S + OFF_DELTA, NROWS, 2048, 128, 160, nullptr);

    // 6. selective scan + silu(g) gating
    scan_k<<<dim3(Dv / 16, 2), 256>>>(
        S + OFF_DBC, S + OFF_DELTA, S + OFF_X1C, S + OFF_PROJ, A_log, S + OFF_YMOD);

    // 7. out_proj + bias + residual -> d_out
    gemm128_k<2><<<dim3(1024 / 128, NROWS / 128), 256>>>(
        S + OFF_YMOD, out_W, out_b, out, NROWS, 1024, 2048, 2048, x);
}

// round 2
// speedup vs baseline: 1.5683x; 1.5683x over previous
#include <cuda_runtime.h>
#include <cstdint>

// ---------------------------------------------------------------------------
// MambaBlock: B=2, T=1024, DM=1024, D=2048, N=16, K=4, DTR=128
// Round 2: all GEMMs on tensor cores (mma.sync m16n8k8 tf32, fp32 accum).
// ---------------------------------------------------------------------------

#define DMv   1024
#define Dv    2048
#define Tv    1024
#define NROWS 2048     // B*T
#define NSTv  16

// Scratch layout (floats)
#define OFF_H      0u          // 2048*1024
#define OFF_PROJ   2097152u    // 2048*4096
#define OFF_X1C    10485760u   // 2048*2048
#define OFF_DBC    14680064u   // 2048*160
#define OFF_DELTA  15007744u   // 2048*2048
#define OFF_YMOD   19202048u   // 2048*2048
#define SCRATCH_FLOATS 23396352u

__device__ __align__(128) float g_scratch[SCRATCH_FLOATS];

__device__ __forceinline__ float silu_f(float v) {
    return v * (1.0f / (1.0f + __expf(-v)));
}

__device__ __forceinline__ unsigned f2tf32(float f) {
    unsigned u;
    asm("cvt.rna.tf32.f32 %0, %1;" : "=r"(u) : "f"(f));
    return u;
}

// ---------------------------------------------------------------------------
// RMSNorm: one block per row (2048 rows), 256 threads, 4 floats/thread
// ---------------------------------------------------------------------------
__global__ void __launch_bounds__(256) rmsnorm_k(
    const float* __restrict__ x, const float* __restrict__ w, float* __restrict__ out)
{
    int row = blockIdx.x;
    const float4* xr = reinterpret_cast<const float4*>(x + (size_t)row * DMv);
    float4 v = xr[threadIdx.x];
    float s = v.x * v.x + v.y * v.y + v.z * v.z + v.w * v.w;
    #pragma unroll
    for (int o = 16; o; o >>= 1) s += __shfl_xor_sync(0xffffffffu, s, o);
    __shared__ float ws[8];
    if ((threadIdx.x & 31) == 0) ws[threadIdx.x >> 5] = s;
    __syncthreads();
    float tot = 0.f;
    #pragma unroll
    for (int i = 0; i < 8; i++) tot += ws[i];
    float scale = rsqrtf(tot * (1.0f / (float)DMv) + 1e-6f);
    float4 wv = reinterpret_cast<const float4*>(w)[threadIdx.x];
    float4 o;
    o.x = v.x * scale * wv.x; o.y = v.y * scale * wv.y;
    o.z = v.z * scale * wv.z; o.w = v.w * scale * wv.w;
    reinterpret_cast<float4*>(out + (size_t)row * DMv)[threadIdx.x] = o;
}

// ---------------------------------------------------------------------------
// Tensor-core GEMM: C[M,N] = A[M,K]@B[K,N] + bias. BM=128, BK=32, BN template.
// 256 threads = 8 warps as 4(M) x 2(N); warp tile 32 x BN/2; mma m16n8k8 tf32.
// EPI 0: none  EPI 1: softplus  EPI 2: + residual (res[M,N]).
// M % 128 == 0, K % 32 == 0, K > 32 required. N guarded (float4 granularity).
// ---------------------------------------------------------------------------
template <int BN, int EPI>
__global__ void __launch_bounds__(256) gemm_tc(
    const float* __restrict__ A, const float* __restrict__ B,
    const float* __restrict__ bias, float* __restrict__ C,
    int N, int Kd, int lda, const float* __restrict__ res)
{
    constexpr int BM = 128, BK = 32;
    constexpr int NB  = BN / 32;   // B float4 loads per thread
    constexpr int WNT = BN / 16;   // n-mma tiles per warp

    __shared__ unsigned As[BK][BM + 8];
    __shared__ unsigned Bs[BK][BN + 8];

    int tid  = threadIdx.x;
    int lane = tid & 31, warp = tid >> 5;
    int wm = warp >> 1, wn = warp & 1;
    int bm = blockIdx.y * BM, bn = blockIdx.x * BN;

    float acc[2][WNT][4];
    #pragma unroll
    for (int i = 0; i < 2; i++)
        #pragma unroll
        for (int j = 0; j < WNT; j++)
            #pragma unroll
            for (int q = 0; q < 4; q++) acc[i][j][q] = 0.f;

    float4 ra[4], rb[NB];

    auto loadAB = [&](int kt) {
        #pragma unroll
        for (int i = 0; i < 4; i++) {
            int li = tid + i * 256;
            int r = li >> 3, k = (li & 7) * 4;
            ra[i] = *reinterpret_cast<const float4*>(&A[(size_t)(bm + r) * lda + kt + k]);
        }
        #pragma unroll
        for (int i = 0; i < NB; i++) {
            int li = tid + i * 256;
            int r = li / (BN / 4), c = (li % (BN / 4)) * 4;
            if (bn + c < N)
                rb[i] = *reinterpret_cast<const float4*>(&B[(size_t)(kt + r) * N + bn + c]);
            else
                rb[i] = make_float4(0.f, 0.f, 0.f, 0.f);
        }
    };
    auto storeAB = [&]() {
        #pragma unroll
        for (int i = 0; i < 4; i++) {
            int li = tid + i * 256;
            int r = li >> 3, k = (li & 7) * 4;
            As[k + 0][r] = f2tf32(ra[i].x); As[k + 1][r] = f2tf32(ra[i].y);
            As[k + 2][r] = f2tf32(ra[i].z); As[k + 3][r] = f2tf32(ra[i].w);
        }
        #pragma unroll
        for (int i = 0; i < NB; i++) {
            int li = tid + i * 256;
            int r = li / (BN / 4), c = (li % (BN / 4)) * 4;
            Bs[r][c + 0] = f2tf32(rb[i].x); Bs[r][c + 1] = f2tf32(rb[i].y);
            Bs[r][c + 2] = f2tf32(rb[i].z); Bs[r][c + 3] = f2tf32(rb[i].w);
        }
    };
    auto compute = [&]() {
        #pragma unroll
        for (int ks = 0; ks < BK / 8; ks++) {
            int k0 = ks * 8;
            unsigned af[2][4];
            #pragma unroll
            for (int mi = 0; mi < 2; mi++) {
                int mr = wm * 32 + mi * 16 + (lane >> 2);
                int kc = k0 + (lane & 3);
                af[mi][0] = As[kc][mr];
                af[mi][1] = As[kc][mr + 8];
                af[mi][2] = As[kc + 4][mr];
                af[mi][3] = As[kc + 4][mr + 8];
            }
            #pragma unroll
            for (int ni = 0; ni < WNT; ni++) {
                int nc = wn * (BN / 2) + ni * 8 + (lane >> 2);
                unsigned b0 = Bs[k0 + (lane & 3)][nc];
                unsigned b1 = Bs[k0 + (lane & 3) + 4][nc];
                #pragma unroll
                for (int mi = 0; mi < 2; mi++) {
                    asm volatile(
                        "mma.sync.aligned.m16n8k8.row.col.f32.tf32.tf32.f32 "
                        "{%0,%1,%2,%3}, {%4,%5,%6,%7}, {%8,%9}, {%0,%1,%2,%3};\n"
                        : "+f"(acc[mi][ni][0]), "+f"(acc[mi][ni][1]),
                          "+f"(acc[mi][ni][2]), "+f"(acc[mi][ni][3])
                        : "r"(af[mi][0]), "r"(af[mi][1]), "r"(af[mi][2]), "r"(af[mi][3]),
                          "r"(b0), "r"(b1));
                }
            }
        }
    };

    loadAB(0);
    storeAB();
    __syncthreads();
    for (int kt = BK; kt < Kd; kt += BK) {
        loadAB(kt);          // prefetch next tile into registers
        compute();           // consume current smem tile
        __syncthreads();
        storeAB();
        __syncthreads();
    }
    compute();

    // Epilogue
    #pragma unroll
    for (int mi = 0; mi < 2; mi++) {
        int r0 = bm + wm * 32 + mi * 16 + (lane >> 2);
        #pragma unroll
        for (int ni = 0; ni < WNT; ni++) {
            int c0 = bn + wn * (BN / 2) + ni * 8 + (lane & 3) * 2;
            #pragma unroll
            for (int h = 0; h < 2; h++) {
                int rr = r0 + h * 8;
                #pragma unroll
                for (int q = 0; q < 2; q++) {
                    int col = c0 + q;
                    if (col >= N) continue;
                    float v = acc[mi][ni][h * 2 + q] + bias[col];
                    if (EPI == 1) v = (v > 20.0f) ? v : log1pf(__expf(v));
                    if (EPI == 2) v += res[(size_t)rr * N + col];
                    C[(size_t)rr * N + col] = v;
                }
            }
        }
    }
}

// ---------------------------------------------------------------------------
// Depthwise causal conv (K=4) + SiLU. x1 = proj[:, 0:2048].
// ---------------------------------------------------------------------------
__global__ void __launch_bounds__(256) conv_silu_k(
    const float* __restrict__ proj, const float* __restrict__ cw,
    const float* __restrict__ cb, float* __restrict__ out)
{
    int d = blockIdx.x * 256 + threadIdx.x;
    int row = blockIdx.y;
    int t = row & (Tv - 1);
    int b = row >> 10;
    float4 w = *reinterpret_cast<const float4*>(cw + (size_t)d * 4);
    float acc = cb[d];
    const float* base = proj + (size_t)(b * Tv) * 4096 + d;
    if (t >= 3) acc = fmaf(base[(size_t)(t - 3) * 4096], w.x, acc);
    if (t >= 2) acc = fmaf(base[(size_t)(t - 2) * 4096], w.y, acc);
    if (t >= 1) acc = fmaf(base[(size_t)(t - 1) * 4096], w.z, acc);
    acc = fmaf(base[(size_t)t * 4096], w.w, acc);
    out[(size_t)row * Dv + d] = silu_f(acc);
}

// ---------------------------------------------------------------------------
// Selective scan. 256 threads = 16 channels x 16 states; fused silu(g) gate.
// ---------------------------------------------------------------------------
__global__ void __launch_bounds__(256) scan_k(
    const float* __restrict__ dbc, const float* __restrict__ delta,
    const float* __restrict__ x1c, const float* __restrict__ proj,
    const float* __restrict__ A_log, float* __restrict__ ymod)
{
    __shared__ float Bs[128][16];
    __shared__ float Cs[128][16];
    __shared__ float Ys[128][16];
    int tid = threadIdx.x;
    int n = tid & 15, grp = tid >> 4;
    int b = blockIdx.y;
    int d = blockIdx.x * 16 + grp;
    float An = -__expf(A_log[(size_t)d * NSTv + n]);   // == -(n+1)
    float h = 0.f;

    for (int c = 0; c < 8; c++) {
        __syncthreads();
        int t0 = c * 128;
        for (int idx = tid; idx < 2048; idx += 256) {
            int tl = idx >> 4, nn = idx & 15;
            size_t r = (size_t)(b * Tv + t0 + tl) * 160;
            Bs[tl][nn] = dbc[r + 128 + nn];
            Cs[tl][nn] = dbc[r + 144 + nn];
        }
        __syncthreads();
        const float* dl = delta + (size_t)(b * Tv + t0) * Dv + d;
        const float* xv = x1c  + (size_t)(b * Tv + t0) * Dv + d;
        #pragma unroll 4
        for (int tl = 0; tl < 128; tl++) {
            float de = dl[(size_t)tl * Dv];
            float xx = xv[(size_t)tl * Dv];
            float a = __expf(de * An);
            h = fmaf(a, h, de * Bs[tl][n] * xx);
            float p = h * Cs[tl][n];
            p += __shfl_xor_sync(0xffffffffu, p, 8);
            p += __shfl_xor_sync(0xffffffffu, p, 4);
            p += __shfl_xor_sync(0xffffffffu, p, 2);
            p += __shfl_xor_sync(0xffffffffu, p, 1);
            if (n == 0) Ys[tl][grp] = p;
        }
        __syncthreads();
        for (int idx = tid; idx < 2048; idx += 256) {
            int tl = idx >> 4, dl2 = idx & 15;
            int row = b * Tv + t0 + tl;
            int dd = blockIdx.x * 16 + dl2;
            float g = proj[(size_t)row * 4096 + 2048 + dd];
            ymod[(size_t)row * Dv + dd] = Ys[tl][dl2] * silu_f(g);
        }
    }
}

// ---------------------------------------------------------------------------
extern "C" void kernel_launch(void* const* d_in, const int* in_sizes, int n_in,
                              void* d_out, int out_size)
{
    const float* x      = (const float*)d_in[0];
    const float* rms_w  = (const float*)d_in[1];
    const float* in_W   = (const float*)d_in[2];
    const float* in_b   = (const float*)d_in[3];
    const float* conv_w = (const float*)d_in[4];
    const float* conv_b = (const float*)d_in[5];
    const float* A_log  = (const float*)d_in[6];
    const float* dbc_W  = (const float*)d_in[7];
    const float* dbc_b  = (const float*)d_in[8];
    const float* dup_W  = (const float*)d_in[9];
    const float* dup_b  = (const float*)d_in[10];
    const float* out_W  = (const float*)d_in[11];
    const float* out_b  = (const float*)d_in[12];
    float* out = (float*)d_out;

    float* S = nullptr;
    cudaGetSymbolAddress((void**)&S, g_scratch);

    // 1. RMSNorm
    rmsnorm_k<<<NROWS, 256>>>(x, rms_w, S + OFF_H);

    // 2. in_proj: (2048x1024)@(1024x4096)
    gemm_tc<128, 0><<<dim3(4096 / 128, NROWS / 128), 256>>>(
        S + OFF_H, in_W, in_b, S + OFF_PROJ, 4096, 1024, 1024, nullptr);

    // 3. depthwise conv + SiLU
    conv_silu_k<<<dim3(Dv / 256, NROWS), 256>>>(S + OFF_PROJ, conv_w, conv_b, S + OFF_X1C);

    // 4. dbc: (2048x2048)@(2048x160)  (BN=64 tensor-core variant, N guarded)
    gemm_tc<64, 0><<<dim3(3, NROWS / 128), 256>>>(
        S + OFF_X1C, dbc_W, dbc_b, S + OFF_DBC, 160, 2048, 2048, nullptr);

    // 5. delta up-proj + softplus: (2048x128)@(128x2048), A rows strided by 160
    gemm_tc<128, 1><<<dim3(2048 / 128, NROWS / 128), 256>>>(
        S + OFF_DBC, dup_W, dup_b, S + OFF_DELTA, 2048, 128, 160, nullptr);

    // 6. selective scan + silu(g) gating
    scan_k<<<dim3(Dv / 16, 2), 256>>>(
        S + OFF_DBC, S + OFF_DELTA, S + OFF_X1C, S + OFF_PROJ, A_log, S + OFF_YMOD);

    // 7. out_proj + bias + residual -> d_out
    gemm_tc<128, 2><<<dim3(1024 / 128, NROWS / 128), 256>>>(
        S + OFF_YMOD, out_W, out_b, out, 1024, 2048, 2048, x);
}

// round 3
// speedup vs baseline: 2.0849x; 1.3294x over previous
#include <cuda_runtime.h>
#include <cstdint>

// ---------------------------------------------------------------------------
// MambaBlock: B=2, T=1024, DM=1024, D=2048, N=16, K=4, DTR=128
// Round 3: cp.async 2-stage pipelined tf32 tensor-core GEMMs, split-K dbc.
// ---------------------------------------------------------------------------

#define DMv   1024
#define Dv    2048
#define Tv    1024
#define NROWS 2048     // B*T
#define NSTv  16

// Scratch layout (floats)
#define OFF_H      0u          // 2048*1024
#define OFF_PROJ   2097152u    // 2048*4096
#define OFF_X1C    10485760u   // 2048*2048
#define OFF_DBC    14680064u   // 2048*160
#define OFF_DELTA  15007744u   // 2048*2048
#define OFF_YMOD   19202048u   // 2048*2048
#define OFF_DBCP   23396352u   // 4 * 2048*160 split-K partials
#define SCRATCH_FLOATS 24707072u

__device__ __align__(128) float g_scratch[SCRATCH_FLOATS];

__device__ __forceinline__ float silu_f(float v) {
    return v * (1.0f / (1.0f + __expf(-v)));
}

__device__ __forceinline__ unsigned f2tf32(float f) {
    unsigned u;
    asm("cvt.rna.tf32.f32 %0, %1;" : "=r"(u) : "f"(f));
    return u;
}

__device__ __forceinline__ void cp16(float* dst, const float* src, bool p) {
    unsigned d = (unsigned)__cvta_generic_to_shared(dst);
    int sz = p ? 16 : 0;
    asm volatile("cp.async.cg.shared.global [%0], [%1], 16, %2;\n"
                 :: "r"(d), "l"(src), "r"(sz));
}

// ---------------------------------------------------------------------------
// RMSNorm
// ---------------------------------------------------------------------------
__global__ void __launch_bounds__(256) rmsnorm_k(
    const float* __restrict__ x, const float* __restrict__ w, float* __restrict__ out)
{
    int row = blockIdx.x;
    const float4* xr = reinterpret_cast<const float4*>(x + (size_t)row * DMv);
    float4 v = xr[threadIdx.x];
    float s = v.x * v.x + v.y * v.y + v.z * v.z + v.w * v.w;
    #pragma unroll
    for (int o = 16; o; o >>= 1) s += __shfl_xor_sync(0xffffffffu, s, o);
    __shared__ float ws[8];
    if ((threadIdx.x & 31) == 0) ws[threadIdx.x >> 5] = s;
    __syncthreads();
    float tot = 0.f;
    #pragma unroll
    for (int i = 0; i < 8; i++) tot += ws[i];
    float scale = rsqrtf(tot * (1.0f / (float)DMv) + 1e-6f);
    float4 wv = reinterpret_cast<const float4*>(w)[threadIdx.x];
    float4 o;
    o.x = v.x * scale * wv.x; o.y = v.y * scale * wv.y;
    o.z = v.z * scale * wv.z; o.w = v.w * scale * wv.w;
    reinterpret_cast<float4*>(out + (size_t)row * DMv)[threadIdx.x] = o;
}

// ---------------------------------------------------------------------------
// Pipelined tf32 tensor-core GEMM.
// C[M,N] = A[M,K]@B[K,N] (+bias) (+epilogue). BM=128, BK=32, BN in {64,128}.
// 256 thr = 8 warps as 4(M)x2(N); warp tile 32 x BN/2; mma m16n8k8 tf32.
// 2-stage cp.async pipeline, dynamic smem.
// EPI 0: +bias   1: +bias,softplus   2: +bias,+res   3: raw (split-K partial)
// blockIdx.z = split-K part: A col-offset part*Kd, B row-offset, C += part*partStride.
// ---------------------------------------------------------------------------
template <int BN, int EPI>
__global__ void __launch_bounds__(256, 2) gemm_tc(
    const float* __restrict__ A, const float* __restrict__ B,
    const float* __restrict__ bias, float* __restrict__ C,
    int N, int Kd, int lda, const float* __restrict__ res, size_t partStride)
{
    constexpr int BM = 128, BK = 32;
    constexpr int ASTR = BK + 8;        // 40  (A stored [m][k], padded)
    constexpr int BSTR = BN + 8;        // B stored [k][n], padded
    constexpr int STAGE = BM * ASTR + BK * BSTR;
    constexpr int WNT = BN / 16;        // n-mma tiles per warp
    constexpr int NBI = (BK * BN / 4) / 256;  // B cp.async per thread

    extern __shared__ float smem[];

    int tid  = threadIdx.x;
    int lane = tid & 31, warp = tid >> 5;
    int wm = warp >> 1, wn = warp & 1;
    int bm = blockIdx.y * BM, bn = blockIdx.x * BN;

    int part = blockIdx.z;
    const float* Ap = A + (size_t)part * Kd;         // column offset
    const float* Bp = B + (size_t)part * Kd * N;     // row offset
    float* Cp = C + (size_t)part * partStride;

    float acc[2][WNT][4];
    #pragma unroll
    for (int i = 0; i < 2; i++)
        #pragma unroll
        for (int j = 0; j < WNT; j++)
            #pragma unroll
            for (int q = 0; q < 4; q++) acc[i][j][q] = 0.f;

    auto issue = [&](int st, int kt) {
        float* As  = smem + st * STAGE;
        float* Bsm = As + BM * ASTR;
        #pragma unroll
        for (int i = 0; i < 4; i++) {
            int li = tid + i * 256;
            int m = li >> 3, k4 = (li & 7) * 4;
            cp16(As + m * ASTR + k4, Ap + (size_t)(bm + m) * lda + kt + k4, true);
        }
        #pragma unroll
        for (int i = 0; i < NBI; i++) {
            int li = tid + i * 256;
            int r, c4;
            if (BN == 128) { r = li >> 5; c4 = (li & 31) * 4; }
            else           { r = li >> 4; c4 = (li & 15) * 4; }
            cp16(Bsm + r * BSTR + c4, Bp + (size_t)(kt + r) * N + bn + c4,
                 (bn + c4) < N);
        }
        asm volatile("cp.async.commit_group;\n" ::: "memory");
    };

    auto compute = [&](int st) {
        const float* As  = smem + st * STAGE;
        const float* Bsm = As + BM * ASTR;
        #pragma unroll
        for (int ks = 0; ks < BK / 8; ks++) {
            int k0 = ks * 8;
            int kc = k0 + (lane & 3);
            unsigned af[2][4];
            #pragma unroll
            for (int mi = 0; mi < 2; mi++) {
                int mr = wm * 32 + mi * 16 + (lane >> 2);
                af[mi][0] = f2tf32(As[mr * ASTR + kc]);
                af[mi][1] = f2tf32(As[(mr + 8) * ASTR + kc]);
                af[mi][2] = f2tf32(As[mr * ASTR + kc + 4]);
                af[mi][3] = f2tf32(As[(mr + 8) * ASTR + kc + 4]);
            }
            #pragma unroll
            for (int ni = 0; ni < WNT; ni++) {
                int nc = wn * (BN / 2) + ni * 8 + (lane >> 2);
                unsigned b0 = f2tf32(Bsm[kc * BSTR + nc]);
                unsigned b1 = f2tf32(Bsm[(kc + 4) * BSTR + nc]);
                #pragma unroll
                for (int mi = 0; mi < 2; mi++) {
                    asm volatile(
                        "mma.sync.aligned.m16n8k8.row.col.f32.tf32.tf32.f32 "
                        "{%0,%1,%2,%3}, {%4,%5,%6,%7}, {%8,%9}, {%0,%1,%2,%3};\n"
                        : "+f"(acc[mi][ni][0]), "+f"(acc[mi][ni][1]),
                          "+f"(acc[mi][ni][2]), "+f"(acc[mi][ni][3])
                        : "r"(af[mi][0]), "r"(af[mi][1]), "r"(af[mi][2]), "r"(af[mi][3]),
                          "r"(b0), "r"(b1));
                }
            }
        }
    };

    int ntiles = Kd / BK;
    issue(0, 0);
    int s = 0;
    for (int i = 0; i < ntiles; i++) {
        asm volatile("cp.async.wait_group 0;\n" ::: "memory");
        __syncthreads();
        if (i + 1 < ntiles) issue(s ^ 1, (i + 1) * BK);
        compute(s);
        s ^= 1;
        if (i + 1 < ntiles) __syncthreads();
    }

    // Epilogue
    #pragma unroll
    for (int mi = 0; mi < 2; mi++) {
        int r0 = bm + wm * 32 + mi * 16 + (lane >> 2);
        #pragma unroll
        for (int ni = 0; ni < WNT; ni++) {
            int c0 = bn + wn * (BN / 2) + ni * 8 + (lane & 3) * 2;
            #pragma unroll
            for (int h = 0; h < 2; h++) {
                int rr = r0 + h * 8;
                #pragma unroll
                for (int q = 0; q < 2; q++) {
                    int col = c0 + q;
                    if (col >= N) continue;
                    float v = acc[mi][ni][h * 2 + q];
                    if (EPI != 3) v += bias[col];
                    if (EPI == 1) v = (v > 20.0f) ? v : log1pf(__expf(v));
                    if (EPI == 2) v += res[(size_t)rr * N + col];
                    Cp[(size_t)rr * N + col] = v;
                }
            }
        }
    }
}

// ---------------------------------------------------------------------------
// Split-K reduce: dbc = sum of 4 partials + bias. 2048*160 elements.
// ---------------------------------------------------------------------------
__global__ void __launch_bounds__(256) reduce4_k(
    const float* __restrict__ P, const float* __restrict__ bias, float* __restrict__ C)
{
    const size_t PS = (size_t)NROWS * 160;
    size_t i = (size_t)blockIdx.x * 256 + threadIdx.x;
    float v = P[i] + P[i + PS] + P[i + 2 * PS] + P[i + 3 * PS] + bias[i % 160];
    C[i] = v;
}

// ---------------------------------------------------------------------------
// Depthwise causal conv (K=4) + SiLU
// ---------------------------------------------------------------------------
__global__ void __launch_bounds__(256) conv_silu_k(
    const float* __restrict__ proj, const float* __restrict__ cw,
    const float* __restrict__ cb, float* __restrict__ out)
{
    int d = blockIdx.x * 256 + threadIdx.x;
    int row = blockIdx.y;
    int t = row & (Tv - 1);
    int b = row >> 10;
    float4 w = *reinterpret_cast<const float4*>(cw + (size_t)d * 4);
    float acc = cb[d];
    const float* base = proj + (size_t)(b * Tv) * 4096 + d;
    if (t >= 3) acc = fmaf(base[(size_t)(t - 3) * 4096], w.x, acc);
    if (t >= 2) acc = fmaf(base[(size_t)(t - 2) * 4096], w.y, acc);
    if (t >= 1) acc = fmaf(base[(size_t)(t - 1) * 4096], w.z, acc);
    acc = fmaf(base[(size_t)t * 4096], w.w, acc);
    out[(size_t)row * Dv + d] = silu_f(acc);
}

// ---------------------------------------------------------------------------
// Selective scan. 256 threads = 16 channels x 16 states; fused silu(g) gate.
// ---------------------------------------------------------------------------
__global__ void __launch_bounds__(256) scan_k(
    const float* __restrict__ dbc, const float* __restrict__ delta,
    const float* __restrict__ x1c, const float* __restrict__ proj,
    const float* __restrict__ A_log, float* __restrict__ ymod)
{
    __shared__ float Bs[128][16];
    __shared__ float Cs[128][16];
    __shared__ float Ys[128][16];
    int tid = threadIdx.x;
    int n = tid & 15, grp = tid >> 4;
    int b = blockIdx.y;
    int d = blockIdx.x * 16 + grp;
    float An = -__expf(A_log[(size_t)d * NSTv + n]);   // == -(n+1)
    float h = 0.f;

    for (int c = 0; c < 8; c++) {
        __syncthreads();
        int t0 = c * 128;
        for (int idx = tid; idx < 2048; idx += 256) {
            int tl = idx >> 4, nn = idx & 15;
            size_t r = (size_t)(b * Tv + t0 + tl) * 160;
            Bs[tl][nn] = dbc[r + 128 + nn];
            Cs[tl][nn] = dbc[r + 144 + nn];
        }
        __syncthreads();
        const float* dl = delta + (size_t)(b * Tv + t0) * Dv + d;
        const float* xv = x1c  + (size_t)(b * Tv + t0) * Dv + d;
        #pragma unroll 4
        for (int tl = 0; tl < 128; tl++) {
            float de = dl[(size_t)tl * Dv];
            float xx = xv[(size_t)tl * Dv];
            float a = __expf(de * An);
            h = fmaf(a, h, de * Bs[tl][n] * xx);
            float p = h * Cs[tl][n];
            p += __shfl_xor_sync(0xffffffffu, p, 8);
            p += __shfl_xor_sync(0xffffffffu, p, 4);
            p += __shfl_xor_sync(0xffffffffu, p, 2);
            p += __shfl_xor_sync(0xffffffffu, p, 1);
            if (n == 0) Ys[tl][grp] = p;
        }
        __syncthreads();
        for (int idx = tid; idx < 2048; idx += 256) {
            int tl = idx >> 4, dl2 = idx & 15;
            int row = b * Tv + t0 + tl;
            int dd = blockIdx.x * 16 + dl2;
            float g = proj[(size_t)row * 4096 + 2048 + dd];
            ymod[(size_t)row * Dv + dd] = Ys[tl][dl2] * silu_f(g);
        }
    }
}

// ---------------------------------------------------------------------------
extern "C" void kernel_launch(void* const* d_in, const int* in_sizes, int n_in,
                              void* d_out, int out_size)
{
    const float* x      = (const float*)d_in[0];
    const float* rms_w  = (const float*)d_in[1];
    const float* in_W   = (const float*)d_in[2];
    const float* in_b   = (const float*)d_in[3];
    const float* conv_w = (const float*)d_in[4];
    const float* conv_b = (const float*)d_in[5];
    const float* A_log  = (const float*)d_in[6];
    const float* dbc_W  = (const float*)d_in[7];
    const float* dbc_b  = (const float*)d_in[8];
    const float* dup_W  = (const float*)d_in[9];
    const float* dup_b  = (const float*)d_in[10];
    const float* out_W  = (const float*)d_in[11];
    const float* out_b  = (const float*)d_in[12];
    float* out = (float*)d_out;

    float* S = nullptr;
    cudaGetSymbolAddress((void**)&S, g_scratch);

    // Dynamic smem: stage = 128*40 + 32*(BN+8) floats, 2 stages
    const int SM128 = 2 * (128 * 40 + 32 * 136) * 4;   // 75776 B
    const int SM64  = 2 * (128 * 40 + 32 * 72) * 4;    // 59392 B
    cudaFuncSetAttribute(gemm_tc<128, 0>, cudaFuncAttributeMaxDynamicSharedMemorySize, SM128);
    cudaFuncSetAttribute(gemm_tc<128, 1>, cudaFuncAttributeMaxDynamicSharedMemorySize, SM128);
    cudaFuncSetAttribute(gemm_tc<64, 2>,  cudaFuncAttributeMaxDynamicSharedMemorySize, SM64);
    cudaFuncSetAttribute(gemm_tc<64, 3>,  cudaFuncAttributeMaxDynamicSharedMemorySize, SM64);

    // 1. RMSNorm
    rmsnorm_k<<<NROWS, 256>>>(x, rms_w, S + OFF_H);

    // 2. in_proj: (2048x1024)@(1024x4096)
    gemm_tc<128, 0><<<dim3(32, 16, 1), 256, SM128>>>(
        S + OFF_H, in_W, in_b, S + OFF_PROJ, 4096, 1024, 1024, nullptr, 0);

    // 3. depthwise conv + SiLU
    conv_silu_k<<<dim3(Dv / 256, NROWS), 256>>>(S + OFF_PROJ, conv_w, conv_b, S + OFF_X1C);

    // 4. dbc: (2048x2048)@(2048x160), split-K x4 -> partials, then reduce
    gemm_tc<64, 3><<<dim3(3, 16, 4), 256, SM64>>>(
        S + OFF_X1C, dbc_W, nullptr, S + OFF_DBCP, 160, 512, 2048, nullptr,
        (size_t)NROWS * 160);
    reduce4_k<<<(NROWS * 160) / 256, 256>>>(S + OFF_DBCP, dbc_b, S + OFF_DBC);

    // 5. delta up-proj + softplus: (2048x128)@(128x2048), A rows strided by 160
    gemm_tc<128, 1><<<dim3(16, 16, 1), 256, SM128>>>(
        S + OFF_DBC, dup_W, dup_b, S + OFF_DELTA, 2048, 128, 160, nullptr, 0);

    // 6. selective scan + silu(g) gating
    scan_k<<<dim3(Dv / 16, 2), 256>>>(
        S + OFF_DBC, S + OFF_DELTA, S + OFF_X1C, S + OFF_PROJ, A_log, S + OFF_YMOD);

    // 7. out_proj + bias + residual -> d_out  (BN=64: grid 256 blocks)
    gemm_tc<64, 2><<<dim3(16, 16, 1), 256, SM64>>>(
        S + OFF_YMOD, out_W, out_b, out, 1024, 2048, 2048, x, 0);
}